// round 2
// baseline (speedup 1.0000x reference)
#include <cuda_runtime.h>
#include <cuda_bf16.h>

// Problem constants (BOWRegressionMulti: T=200, B=1024, V=50000, L=512, PAD=1)
#define T_TOK 200
#define B_SZ  1024
#define V_SZ  50000
#define L_SZ  512
#define PAD_TOK 1

// Scratch: transposed weights Wt[V][L] (102.4 MB, static device global — no allocs)
__device__ float g_Wt[(size_t)V_SZ * L_SZ];

// ---------------------------------------------------------------------------
// Kernel 1: tiled transpose W[L,V] -> Wt[V,L], coalesced on both sides.
// ---------------------------------------------------------------------------
__global__ void bow_transpose_kernel(const float* __restrict__ W) {
    __shared__ float tile[32][33];
    const int v0 = blockIdx.x * 32;   // vocab tile base
    const int l0 = blockIdx.y * 32;   // label tile base (L=512 divides evenly)

    // Read: W[l0+i][v0+tx], contiguous in v (tx)
    #pragma unroll
    for (int i = threadIdx.y; i < 32; i += 8) {
        int v = v0 + threadIdx.x;
        if (v < V_SZ) {
            tile[i][threadIdx.x] = W[(size_t)(l0 + i) * V_SZ + v];
        }
    }
    __syncthreads();

    // Write: Wt[v0+i][l0+tx], contiguous in l (tx)
    #pragma unroll
    for (int i = threadIdx.y; i < 32; i += 8) {
        int v = v0 + i;
        if (v < V_SZ) {
            g_Wt[(size_t)v * L_SZ + l0 + threadIdx.x] = tile[threadIdx.x][i];
        }
    }
}

// ---------------------------------------------------------------------------
// Kernel 2: per-batch-row dedupe + gather-reduce.
// One block = one batch row. 128 threads; thread t owns labels [4t, 4t+4)
// via float4. Dedupe via shared bitmap + atomicOr (first setter appends to a
// compact token list), then acc += Wt[v][4t..4t+3] for each distinct token.
// ---------------------------------------------------------------------------
__global__ __launch_bounds__(128) void bow_gather_kernel(
    const int* __restrict__ text,         // [T, B] int32 (JAX x64-off downcast)
    const float* __restrict__ bias,       // [L]
    float* __restrict__ out)              // [B, L]
{
    __shared__ unsigned int bitmap[(V_SZ + 31) / 32];  // 1563 words = 6.25 KB
    __shared__ int toks[T_TOK];
    __shared__ int cnt;

    const int b   = blockIdx.x;
    const int tid = threadIdx.x;

    for (int i = tid; i < (V_SZ + 31) / 32; i += 128) bitmap[i] = 0u;
    if (tid == 0) cnt = 0;
    __syncthreads();

    // Dedupe the 200 tokens of this row (text is [T,B]: stride B between t's)
    #pragma unroll 2
    for (int t = tid; t < T_TOK; t += 128) {
        int v = text[(size_t)t * B_SZ + b];
        if (v != PAD_TOK && (unsigned)v < (unsigned)V_SZ) {
            unsigned int bit = 1u << (v & 31);
            unsigned int old = atomicOr(&bitmap[v >> 5], bit);
            if (!(old & bit)) {
                int idx = atomicAdd(&cnt, 1);
                toks[idx] = v;
            }
        }
    }
    __syncthreads();

    const int n = cnt;

    // 4 independent accumulators for MLP; bias-initialized.
    float4 acc0 = ((const float4*)bias)[tid];
    float4 acc1 = make_float4(0.f, 0.f, 0.f, 0.f);
    float4 acc2 = make_float4(0.f, 0.f, 0.f, 0.f);
    float4 acc3 = make_float4(0.f, 0.f, 0.f, 0.f);

    int j = 0;
    for (; j + 4 <= n; j += 4) {
        const float4 w0 = ((const float4*)(g_Wt + (size_t)toks[j + 0] * L_SZ))[tid];
        const float4 w1 = ((const float4*)(g_Wt + (size_t)toks[j + 1] * L_SZ))[tid];
        const float4 w2 = ((const float4*)(g_Wt + (size_t)toks[j + 2] * L_SZ))[tid];
        const float4 w3 = ((const float4*)(g_Wt + (size_t)toks[j + 3] * L_SZ))[tid];
        acc0.x += w0.x; acc0.y += w0.y; acc0.z += w0.z; acc0.w += w0.w;
        acc1.x += w1.x; acc1.y += w1.y; acc1.z += w1.z; acc1.w += w1.w;
        acc2.x += w2.x; acc2.y += w2.y; acc2.z += w2.z; acc2.w += w2.w;
        acc3.x += w3.x; acc3.y += w3.y; acc3.z += w3.z; acc3.w += w3.w;
    }
    for (; j < n; j++) {
        const float4 w = ((const float4*)(g_Wt + (size_t)toks[j] * L_SZ))[tid];
        acc0.x += w.x; acc0.y += w.y; acc0.z += w.z; acc0.w += w.w;
    }

    float4 r;
    r.x = (acc0.x + acc1.x) + (acc2.x + acc3.x);
    r.y = (acc0.y + acc1.y) + (acc2.y + acc3.y);
    r.z = (acc0.z + acc1.z) + (acc2.z + acc3.z);
    r.w = (acc0.w + acc1.w) + (acc2.w + acc3.w);

    ((float4*)out)[(size_t)b * (L_SZ / 4) + tid] = r;
}

// ---------------------------------------------------------------------------
// Launch: transpose then gather, same stream (graph-capturable, no syncs).
// Inputs per metadata: [0] text int32 [T,B], [1] W f32 [L,V], [2] b f32 [L].
// ---------------------------------------------------------------------------
extern "C" void kernel_launch(void* const* d_in, const int* in_sizes, int n_in,
                              void* d_out, int out_size) {
    const int*   text = (const int*)d_in[0];
    const float* W    = (const float*)d_in[1];
    const float* bias = (const float*)d_in[2];
    float*       out  = (float*)d_out;

    dim3 tgrid((V_SZ + 31) / 32, L_SZ / 32);
    dim3 tblock(32, 8);
    bow_transpose_kernel<<<tgrid, tblock>>>(W);

    bow_gather_kernel<<<B_SZ, 128>>>(text, bias, out);
}

// round 3
// speedup vs baseline: 1.6727x; 1.6727x over previous
#include <cuda_runtime.h>
#include <cuda_fp16.h>

// Problem constants (BOWRegressionMulti: T=200, B=1024, V=50000, L=512, PAD=1)
#define T_TOK 200
#define B_SZ  1024
#define V_SZ  50000
#define L_SZ  512
#define PAD_TOK 1

// Scratch: transposed weights in fp16, Wt[V][L] (51.2 MB static — L2-resident)
__device__ __half g_Wt_h[(size_t)V_SZ * L_SZ];

// ---------------------------------------------------------------------------
// Kernel 1: tiled transpose + fp32->fp16 convert. W[L,V] f32 -> Wt[V,L] f16.
// 64(l) x 64(v) tiles, 256 threads. float4 global loads, uint4 (8xfp16) stores.
// ---------------------------------------------------------------------------
__global__ __launch_bounds__(256) void bow_transpose_f16_kernel(
    const float* __restrict__ W)
{
    __shared__ float tile[64][65];           // [l][v], +1 pad
    const int v0  = blockIdx.x * 64;
    const int l0  = blockIdx.y * 64;         // L=512 divides by 64 exactly
    const int tid = threadIdx.x;

    // ---- Read: 64 l-rows x 16 float4 along v. 4 passes of 16 rows. ----
    {
        const int tx = tid & 15;             // float4 slot in row
        const int ty = tid >> 4;             // row within 16-row pass
        const int v  = v0 + tx * 4;          // V divisible by 4 -> all-or-none
        #pragma unroll
        for (int p = 0; p < 4; p++) {
            const int l = ty + p * 16;
            float4 val = make_float4(0.f, 0.f, 0.f, 0.f);
            if (v < V_SZ) {
                val = *(const float4*)(W + (size_t)(l0 + l) * V_SZ + v);
            }
            tile[l][tx * 4 + 0] = val.x;
            tile[l][tx * 4 + 1] = val.y;
            tile[l][tx * 4 + 2] = val.z;
            tile[l][tx * 4 + 3] = val.w;
        }
    }
    __syncthreads();

    // ---- Write: 64 v-rows x 8 uint4 (8 fp16 each) along l. 2 passes. ----
    {
        const int wx = tid & 7;              // which 8-label chunk
        const int wy = tid >> 3;             // v row within 32-row pass
        #pragma unroll
        for (int p = 0; p < 2; p++) {
            const int vr = wy + p * 32;
            const int v  = v0 + vr;
            if (v < V_SZ) {
                const int lbase = wx * 8;
                __half2 h[4];
                #pragma unroll
                for (int k = 0; k < 4; k++) {
                    h[k] = __floats2half2_rn(tile[lbase + 2 * k][vr],
                                             tile[lbase + 2 * k + 1][vr]);
                }
                uint4 pkt;
                pkt.x = *(unsigned int*)&h[0];
                pkt.y = *(unsigned int*)&h[1];
                pkt.z = *(unsigned int*)&h[2];
                pkt.w = *(unsigned int*)&h[3];
                *(uint4*)(g_Wt_h + (size_t)v * L_SZ + l0 + lbase) = pkt;
            }
        }
    }
}

// ---------------------------------------------------------------------------
// Kernel 2: per-batch-row dedupe + fp16 gather-reduce (fp32 accumulators).
// One block = one batch row. 128 threads; thread t owns labels [4t, 4t+4).
// ---------------------------------------------------------------------------
__global__ __launch_bounds__(128) void bow_gather_kernel(
    const int* __restrict__ text,         // [T, B] int32
    const float* __restrict__ bias,       // [L]
    float* __restrict__ out)              // [B, L]
{
    __shared__ unsigned int bitmap[(V_SZ + 31) / 32];  // 6.25 KB
    __shared__ int toks[T_TOK];
    __shared__ int cnt;

    const int b   = blockIdx.x;
    const int tid = threadIdx.x;

    for (int i = tid; i < (V_SZ + 31) / 32; i += 128) bitmap[i] = 0u;
    if (tid == 0) cnt = 0;
    __syncthreads();

    // Dedupe the 200 tokens of this row (text is [T,B]: stride B between t's)
    #pragma unroll 2
    for (int t = tid; t < T_TOK; t += 128) {
        int v = text[(size_t)t * B_SZ + b];
        if (v != PAD_TOK && (unsigned)v < (unsigned)V_SZ) {
            unsigned int bit = 1u << (v & 31);
            unsigned int old = atomicOr(&bitmap[v >> 5], bit);
            if (!(old & bit)) {
                int idx = atomicAdd(&cnt, 1);
                toks[idx] = v;
            }
        }
    }
    __syncthreads();

    const int n = cnt;

    // 4 independent fp32 accumulators (MLP=4 outstanding 8B gathers).
    float4 acc0 = ((const float4*)bias)[tid];
    float4 acc1 = make_float4(0.f, 0.f, 0.f, 0.f);
    float4 acc2 = make_float4(0.f, 0.f, 0.f, 0.f);
    float4 acc3 = make_float4(0.f, 0.f, 0.f, 0.f);

    int j = 0;
    for (; j + 4 <= n; j += 4) {
        const uint2 u0 = ((const uint2*)(g_Wt_h + (size_t)toks[j + 0] * L_SZ))[tid];
        const uint2 u1 = ((const uint2*)(g_Wt_h + (size_t)toks[j + 1] * L_SZ))[tid];
        const uint2 u2 = ((const uint2*)(g_Wt_h + (size_t)toks[j + 2] * L_SZ))[tid];
        const uint2 u3 = ((const uint2*)(g_Wt_h + (size_t)toks[j + 3] * L_SZ))[tid];

        float2 a, c;
        a = __half22float2(*(const __half2*)&u0.x); c = __half22float2(*(const __half2*)&u0.y);
        acc0.x += a.x; acc0.y += a.y; acc0.z += c.x; acc0.w += c.y;
        a = __half22float2(*(const __half2*)&u1.x); c = __half22float2(*(const __half2*)&u1.y);
        acc1.x += a.x; acc1.y += a.y; acc1.z += c.x; acc1.w += c.y;
        a = __half22float2(*(const __half2*)&u2.x); c = __half22float2(*(const __half2*)&u2.y);
        acc2.x += a.x; acc2.y += a.y; acc2.z += c.x; acc2.w += c.y;
        a = __half22float2(*(const __half2*)&u3.x); c = __half22float2(*(const __half2*)&u3.y);
        acc3.x += a.x; acc3.y += a.y; acc3.z += c.x; acc3.w += c.y;
    }
    for (; j < n; j++) {
        const uint2 u = ((const uint2*)(g_Wt_h + (size_t)toks[j] * L_SZ))[tid];
        float2 a = __half22float2(*(const __half2*)&u.x);
        float2 c = __half22float2(*(const __half2*)&u.y);
        acc0.x += a.x; acc0.y += a.y; acc0.z += c.x; acc0.w += c.y;
    }

    float4 r;
    r.x = (acc0.x + acc1.x) + (acc2.x + acc3.x);
    r.y = (acc0.y + acc1.y) + (acc2.y + acc3.y);
    r.z = (acc0.z + acc1.z) + (acc2.z + acc3.z);
    r.w = (acc0.w + acc1.w) + (acc2.w + acc3.w);

    ((float4*)out)[(size_t)b * (L_SZ / 4) + tid] = r;
}

// ---------------------------------------------------------------------------
// Launch: transpose+convert then gather (graph-capturable, no syncs).
// Inputs: [0] text int32 [T,B], [1] W f32 [L,V], [2] b f32 [L].
// ---------------------------------------------------------------------------
extern "C" void kernel_launch(void* const* d_in, const int* in_sizes, int n_in,
                              void* d_out, int out_size) {
    const int*   text = (const int*)d_in[0];
    const float* W    = (const float*)d_in[1];
    const float* bias = (const float*)d_in[2];
    float*       out  = (float*)d_out;

    dim3 tgrid((V_SZ + 63) / 64, L_SZ / 64);   // 782 x 8
    bow_transpose_f16_kernel<<<tgrid, 256>>>(W);

    bow_gather_kernel<<<B_SZ, 128>>>(text, bias, out);
}

// round 4
// speedup vs baseline: 2.0650x; 1.2345x over previous
#include <cuda_runtime.h>
#include <cuda_fp16.h>

// Problem constants (BOWRegressionMulti: T=200, B=1024, V=50000, L=512, PAD=1)
#define T_TOK 200
#define B_SZ  1024
#define V_SZ  50000
#define L_SZ  512
#define PAD_TOK 1

// Scratch: transposed weights in fp16, Wt[V][L] (51.2 MB static — L2-resident)
__device__ __half g_Wt_h[(size_t)V_SZ * L_SZ];

// ---------------------------------------------------------------------------
// Kernel 1: tiled transpose + fp32->fp16 convert. W[L,V] f32 -> Wt[V,L] f16.
// 64(l) x 64(v) tiles, 256 threads. __ldcs float4 loads (W is single-use —
// keep it out of L2 so Wt stays resident for the gather), uint4 stores.
// ---------------------------------------------------------------------------
__global__ __launch_bounds__(256) void bow_transpose_f16_kernel(
    const float* __restrict__ W)
{
    __shared__ float tile[64][65];           // [l][v], +1 pad
    const int v0  = blockIdx.x * 64;
    const int l0  = blockIdx.y * 64;         // L=512 divides by 64 exactly
    const int tid = threadIdx.x;

    // ---- Read: 64 l-rows x 16 float4 along v. 4 passes of 16 rows. ----
    {
        const int tx = tid & 15;             // float4 slot in row
        const int ty = tid >> 4;             // row within 16-row pass
        const int v  = v0 + tx * 4;          // V divisible by 4 -> all-or-none
        #pragma unroll
        for (int p = 0; p < 4; p++) {
            const int l = ty + p * 16;
            float4 val = make_float4(0.f, 0.f, 0.f, 0.f);
            if (v < V_SZ) {
                val = __ldcs((const float4*)(W + (size_t)(l0 + l) * V_SZ + v));
            }
            tile[l][tx * 4 + 0] = val.x;
            tile[l][tx * 4 + 1] = val.y;
            tile[l][tx * 4 + 2] = val.z;
            tile[l][tx * 4 + 3] = val.w;
        }
    }
    __syncthreads();

    // ---- Write: 64 v-rows x 8 uint4 (8 fp16 each) along l. 2 passes. ----
    {
        const int wx = tid & 7;              // which 8-label chunk
        const int wy = tid >> 3;             // v row within 32-row pass
        #pragma unroll
        for (int p = 0; p < 2; p++) {
            const int vr = wy + p * 32;
            const int v  = v0 + vr;
            if (v < V_SZ) {
                const int lbase = wx * 8;
                __half2 h[4];
                #pragma unroll
                for (int k = 0; k < 4; k++) {
                    h[k] = __floats2half2_rn(tile[lbase + 2 * k][vr],
                                             tile[lbase + 2 * k + 1][vr]);
                }
                uint4 pkt;
                pkt.x = *(unsigned int*)&h[0];
                pkt.y = *(unsigned int*)&h[1];
                pkt.z = *(unsigned int*)&h[2];
                pkt.w = *(unsigned int*)&h[3];
                *(uint4*)(g_Wt_h + (size_t)v * L_SZ + l0 + lbase) = pkt;
            }
        }
    }
}

// ---------------------------------------------------------------------------
// Kernel 2: per-batch-row dedupe + fp16 gather-reduce (fp32 accumulators).
// One block = one batch row. 256 threads (8 warps -> ~86% occ at grid=1024);
// thread t owns labels [2t, 2t+1] via one 4B half2 load per token.
// 8 independent accumulators keep 8 gathers in flight per thread.
// ---------------------------------------------------------------------------
__global__ __launch_bounds__(256) void bow_gather_kernel(
    const int* __restrict__ text,         // [T, B] int32
    const float* __restrict__ bias,       // [L]
    float* __restrict__ out)              // [B, L]
{
    __shared__ unsigned int bitmap[(V_SZ + 31) / 32];  // 6.25 KB
    __shared__ int toks[T_TOK];
    __shared__ int cnt;

    const int b   = blockIdx.x;
    const int tid = threadIdx.x;

    for (int i = tid; i < (V_SZ + 31) / 32; i += 256) bitmap[i] = 0u;
    if (tid == 0) cnt = 0;
    __syncthreads();

    // Dedupe the 200 tokens of this row (text is [T,B]: stride B between t's)
    if (tid < T_TOK) {
        int v = text[(size_t)tid * B_SZ + b];
        if (v != PAD_TOK && (unsigned)v < (unsigned)V_SZ) {
            unsigned int bit = 1u << (v & 31);
            unsigned int old = atomicOr(&bitmap[v >> 5], bit);
            if (!(old & bit)) {
                int idx = atomicAdd(&cnt, 1);
                toks[idx] = v;
            }
        }
    }
    __syncthreads();

    const int n = cnt;
    const __half* Wt = g_Wt_h;

    // 8 independent fp32 accumulators (MLP=8 outstanding 4B gathers/thread).
    float2 a0 = ((const float2*)bias)[tid];
    float2 a1 = make_float2(0.f, 0.f);
    float2 a2 = make_float2(0.f, 0.f);
    float2 a3 = make_float2(0.f, 0.f);
    float2 a4 = make_float2(0.f, 0.f);
    float2 a5 = make_float2(0.f, 0.f);
    float2 a6 = make_float2(0.f, 0.f);
    float2 a7 = make_float2(0.f, 0.f);

    int j = 0;
    for (; j + 8 <= n; j += 8) {
        unsigned int u0 = ((const unsigned int*)(Wt + (size_t)toks[j + 0] * L_SZ))[tid];
        unsigned int u1 = ((const unsigned int*)(Wt + (size_t)toks[j + 1] * L_SZ))[tid];
        unsigned int u2 = ((const unsigned int*)(Wt + (size_t)toks[j + 2] * L_SZ))[tid];
        unsigned int u3 = ((const unsigned int*)(Wt + (size_t)toks[j + 3] * L_SZ))[tid];
        unsigned int u4 = ((const unsigned int*)(Wt + (size_t)toks[j + 4] * L_SZ))[tid];
        unsigned int u5 = ((const unsigned int*)(Wt + (size_t)toks[j + 5] * L_SZ))[tid];
        unsigned int u6 = ((const unsigned int*)(Wt + (size_t)toks[j + 6] * L_SZ))[tid];
        unsigned int u7 = ((const unsigned int*)(Wt + (size_t)toks[j + 7] * L_SZ))[tid];
        float2 f;
        f = __half22float2(*(const __half2*)&u0); a0.x += f.x; a0.y += f.y;
        f = __half22float2(*(const __half2*)&u1); a1.x += f.x; a1.y += f.y;
        f = __half22float2(*(const __half2*)&u2); a2.x += f.x; a2.y += f.y;
        f = __half22float2(*(const __half2*)&u3); a3.x += f.x; a3.y += f.y;
        f = __half22float2(*(const __half2*)&u4); a4.x += f.x; a4.y += f.y;
        f = __half22float2(*(const __half2*)&u5); a5.x += f.x; a5.y += f.y;
        f = __half22float2(*(const __half2*)&u6); a6.x += f.x; a6.y += f.y;
        f = __half22float2(*(const __half2*)&u7); a7.x += f.x; a7.y += f.y;
    }
    for (; j < n; j++) {
        unsigned int u = ((const unsigned int*)(Wt + (size_t)toks[j] * L_SZ))[tid];
        float2 f = __half22float2(*(const __half2*)&u);
        a0.x += f.x; a0.y += f.y;
    }

    float2 r;
    r.x = ((a0.x + a1.x) + (a2.x + a3.x)) + ((a4.x + a5.x) + (a6.x + a7.x));
    r.y = ((a0.y + a1.y) + (a2.y + a3.y)) + ((a4.y + a5.y) + (a6.y + a7.y));

    ((float2*)out)[(size_t)b * (L_SZ / 2) + tid] = r;
}

// ---------------------------------------------------------------------------
// Launch: transpose+convert then gather (graph-capturable, no syncs).
// Inputs: [0] text int32 [T,B], [1] W f32 [L,V], [2] b f32 [L].
// ---------------------------------------------------------------------------
extern "C" void kernel_launch(void* const* d_in, const int* in_sizes, int n_in,
                              void* d_out, int out_size) {
    const int*   text = (const int*)d_in[0];
    const float* W    = (const float*)d_in[1];
    const float* bias = (const float*)d_in[2];
    float*       out  = (float*)d_out;

    dim3 tgrid((V_SZ + 63) / 64, L_SZ / 64);   // 782 x 8
    bow_transpose_f16_kernel<<<tgrid, 256>>>(W);

    bow_gather_kernel<<<B_SZ, 256>>>(text, bias, out);
}